// round 15
// baseline (speedup 1.0000x reference)
#include <cuda_runtime.h>
#include <cuda_bf16.h>
#include <cstdint>

#define NTOK 16384
#define HD   2048
#define NE   8
#define BD   128
#define EPSF 1e-6f

// ---------------- static device scratch ----------------
__device__ __nv_bfloat16 g_xb [NTOK * HD];
__device__ __nv_bfloat16 g_w1b[NE * BD * HD];
__device__ __nv_bfloat16 g_w2b[NE * HD * BD];
__device__ __nv_bfloat16 g_scr[2 * NTOK * HD];
__device__ float g_w   [NTOK * NE];
__device__ float g_pp  [(NTOK / 8) * NE];
__device__ int   g_tok [NE * NTOK];
__device__ int   g_cnt [NE];

// ---------------- helpers ----------------
static __device__ __forceinline__ uint32_t smem_u32(const void* p) {
    return (uint32_t)__cvta_generic_to_shared(p);
}
#define CP16(dst_u32, src_ptr) \
    asm volatile("cp.async.cg.shared.global [%0], [%1], 16;\n" :: "r"(dst_u32), "l"(src_ptr))
#define CP_COMMIT() asm volatile("cp.async.commit_group;\n" ::)
#define CP_WAIT(n)  asm volatile("cp.async.wait_group %0;\n" :: "n"(n))

static __device__ __forceinline__ void ldm4(uint32_t& r0, uint32_t& r1, uint32_t& r2, uint32_t& r3,
                                            uint32_t addr) {
    asm volatile("ldmatrix.sync.aligned.m8n8.x4.shared.b16 {%0,%1,%2,%3}, [%4];"
                 : "=r"(r0), "=r"(r1), "=r"(r2), "=r"(r3) : "r"(addr));
}
static __device__ __forceinline__ void mma16816(float* c, const uint32_t* a, const uint32_t* b) {
    asm volatile(
        "mma.sync.aligned.m16n8k16.row.col.f32.bf16.bf16.f32 "
        "{%0,%1,%2,%3}, {%4,%5,%6,%7}, {%8,%9}, {%0,%1,%2,%3};"
        : "+f"(c[0]), "+f"(c[1]), "+f"(c[2]), "+f"(c[3])
        : "r"(a[0]), "r"(a[1]), "r"(a[2]), "r"(a[3]), "r"(b[0]), "r"(b[1]));
}
// packed fp32x2 math
static __device__ __forceinline__ unsigned long long f2mul(unsigned long long a, unsigned long long b) {
    unsigned long long d;
    asm("mul.rn.f32x2 %0, %1, %2;" : "=l"(d) : "l"(a), "l"(b));
    return d;
}
static __device__ __forceinline__ unsigned long long f2fma(unsigned long long a, unsigned long long b,
                                                           unsigned long long c) {
    unsigned long long d;
    asm("fma.rn.f32x2 %0, %1, %2, %3;" : "=l"(d) : "l"(a), "l"(b), "l"(c));
    return d;
}

// ---------------- no-op pads (so ncu slot 4 = k_router) ----------------
__global__ void k_nopA() {}
__global__ void k_nopB() {}

// ---------------- kernel: weights -> bf16 (+ counter init) ----------------
__global__ void k_convert(const float* __restrict__ W1, const float* __restrict__ W2) {
    if (blockIdx.x == 0 && threadIdx.x < NE) g_cnt[threadIdx.x] = 0;
    int total = NE * BD * HD;
    for (int i = blockIdx.x * blockDim.x + threadIdx.x; i < total; i += gridDim.x * blockDim.x) {
        g_w1b[i] = __float2bfloat16(W1[i]);
        g_w2b[i] = __float2bfloat16(W2[i]);
    }
}

// ---------------- kernel: router v5 (32 tokens/block; 4 experts/warp; f32x2 FMA) ----------------
#define RT 32
__global__ __launch_bounds__(512, 2) void k_router(const float* __restrict__ x,
                                                   const float* __restrict__ skin,
                                                   const float* __restrict__ Wimg,
                                                   const float* __restrict__ Wskin) {
    int nb = blockIdx.x * RT;
    int tid = threadIdx.x, lane = tid & 31, wid = tid >> 5;
    int eg = wid >> 3;   // expert group: experts [eg*4, eg*4+4)
    int wc = wid & 7;    // column chunk: cols [wc*256, wc*256+256)

    __shared__ float part[16][RT][4];
    __shared__ float lg[RT][NE];
    __shared__ float sp[RT][NE];
    __shared__ int   sel[2][RT];

    // 1) bf16 conversion pass (coalesced; populates caches for the dot pass)
    {
        const float4* xs4 = (const float4*)(x + (size_t)nb * HD);
        uint2* xd = (uint2*)(g_xb + (size_t)nb * HD);
#pragma unroll
        for (int k = 0; k < RT * HD / 4 / 512; k++) {
            int i = tid + k * 512;
            float4 a = xs4[i];
            uint32_t lo, hi;
            asm("cvt.rn.bf16x2.f32 %0, %1, %2;" : "=r"(lo) : "f"(a.y), "f"(a.x));
            asm("cvt.rn.bf16x2.f32 %0, %1, %2;" : "=r"(hi) : "f"(a.w), "f"(a.z));
            xd[i] = make_uint2(lo, hi);
        }
    }

    // 2) this warp's W_img chunk: 4 experts x 8 cols per lane (f32x2 pairs)
    int base = wc * 256 + lane * 8;
    ulonglong2 w0[4], w1[4];
#pragma unroll
    for (int je = 0; je < 4; je++) {
        int e = eg * 4 + je;
        w0[je] = *(const ulonglong2*)(Wimg + (size_t)e * HD + base);
        w1[je] = *(const ulonglong2*)(Wimg + (size_t)e * HD + base + 4);
    }

    // 3) per-token dots (4 experts per warp) + transpose-reduce
    for (int t = 0; t < RT; t++) {
        const ulonglong2* xr = (const ulonglong2*)(x + (size_t)(nb + t) * HD + base);
        ulonglong2 a0 = xr[0];
        ulonglong2 a1 = xr[1];
        float v[4];
#pragma unroll
        for (int je = 0; je < 4; je++) {
            unsigned long long acc = f2mul(a0.x, w0[je].x);
            acc = f2fma(a0.y, w0[je].y, acc);
            acc = f2fma(a1.x, w1[je].x, acc);
            acc = f2fma(a1.y, w1[je].y, acc);
            float flo, fhi;
            asm("mov.b64 {%0, %1}, %2;" : "=f"(flo), "=f"(fhi) : "l"(acc));
            v[je] = flo + fhi;
        }
        {
            int bit = lane & 1;
            float s0 = __shfl_xor_sync(0xffffffffu, bit ? v[0] : v[2], 1);
            float s1 = __shfl_xor_sync(0xffffffffu, bit ? v[1] : v[3], 1);
            v[0] = (bit ? v[2] : v[0]) + s0;
            v[1] = (bit ? v[3] : v[1]) + s1;
        }
        {
            int bit = (lane >> 1) & 1;
            float s0 = __shfl_xor_sync(0xffffffffu, bit ? v[0] : v[1], 2);
            v[0] = (bit ? v[1] : v[0]) + s0;
        }
        v[0] += __shfl_xor_sync(0xffffffffu, v[0], 4);
        v[0] += __shfl_xor_sync(0xffffffffu, v[0], 8);
        v[0] += __shfl_xor_sync(0xffffffffu, v[0], 16);
        if (lane < 4) {
            int je = ((lane & 1) << 1) | ((lane >> 1) & 1);
            part[wid][t][je] = v[0];
        }
    }
    __syncthreads();

    // 4) cross-warp combine + skin term  (RT*NE = 256 threads)
    if (tid < RT * NE) {
        int t = tid >> 3, e = tid & 7;
        int eg2 = e >> 2, je = e & 3;
        float s = 0.f;
#pragma unroll
        for (int w = 0; w < 8; w++) s += part[eg2 * 8 + w][t][je];
        int n = nb + t;
        s += skin[n * 3 + 0] * Wskin[e * 3 + 0] +
             skin[n * 3 + 1] * Wskin[e * 3 + 1] +
             skin[n * 3 + 2] * Wskin[e * 3 + 2];
        lg[t][e] = s;
    }
    __syncthreads();

    // 5) softmax + top-2 per token
    if (tid < RT) {
        int t = tid, n = nb + t;
        float p[NE];
        float mx = lg[t][0];
#pragma unroll
        for (int e = 1; e < NE; e++) mx = fmaxf(mx, lg[t][e]);
        float ssum = 0.f;
#pragma unroll
        for (int e = 0; e < NE; e++) { p[e] = expf(lg[t][e] - mx); ssum += p[e]; }
        float inv = 1.f / ssum;
#pragma unroll
        for (int e = 0; e < NE; e++) p[e] *= inv;

        int i1 = 0;
#pragma unroll
        for (int e = 1; e < NE; e++) if (p[e] > p[i1]) i1 = e;
        int i2 = (i1 == 0) ? 1 : 0;
#pragma unroll
        for (int e = 0; e < NE; e++) { if (e != i1 && p[e] > p[i2]) i2 = e; }

        float v1 = p[i1], v2 = p[i2];
        float wn = 1.f / (v1 + v2 + EPSF);
        float wv[NE];
#pragma unroll
        for (int e = 0; e < NE; e++) wv[e] = 0.f;
        wv[i1] = v1 * wn;
        wv[i2] = v2 * wn;
#pragma unroll
        for (int e = 0; e < NE; e++) { g_w[n * NE + e] = wv[e]; sp[t][e] = p[e]; }

        sel[0][t] = i1;
        sel[1][t] = i2;
    }
    __syncthreads();

    // 6) per-expert scatter: one independent atomic per (block, expert)
    if (tid < NE) {
        int e = tid;
        int cnt = 0;
#pragma unroll
        for (int t = 0; t < RT; t++) cnt += (sel[0][t] == e) + (sel[1][t] == e);
        if (cnt) {
            int bse = atomicAdd(&g_cnt[e], cnt);
            int o = 0;
#pragma unroll
            for (int t = 0; t < RT; t++) {
                if (sel[0][t] == e) g_tok[e * NTOK + bse + (o++)] = (nb + t) * 2;
                if (sel[1][t] == e) g_tok[e * NTOK + bse + (o++)] = (nb + t) * 2 + 1;
            }
        }
    }

    // 7) per-block prob partials for aux loss (deterministic)
    if (tid >= 32 && tid < 32 + NE) {
        int e = tid - 32;
        float s = 0.f;
#pragma unroll
        for (int t = 0; t < RT; t++) s += sp[t][e];
        g_pp[blockIdx.x * NE + e] = s;
    }
}

// ---------------- kernel: fused MoE expert, 512 threads, phase-1 K-stage 64 x 3 buffers ----------------
#define FM_SMEM 112640
__global__ __launch_bounds__(512, 2) void k_moe(const float* __restrict__ b1,
                                                const float* __restrict__ b2) {
    extern __shared__ __align__(16) char sm[];
    // phase 1: 3 stages, each A[128][72] + B[128][72] bf16 (36864 B/stage)
    __nv_bfloat16 (*As)[128][72] = (__nv_bfloat16 (*)[128][72])sm;            // stride 36864
    // phase 2 layout (reused region)
    __nv_bfloat16 (*H)[136]        = (__nv_bfloat16 (*)[136])sm;
    __nv_bfloat16 (*W2s)[128][136] = (__nv_bfloat16 (*)[128][136])(sm + 34816);
    float* b2s = (float*)(sm + 104448);

    __shared__ int   vrow[128];
    __shared__ float wrow[128];

    int e = blockIdx.y;
    int cnt = g_cnt[e];
    int m0 = blockIdx.x * 128;
    if (m0 >= cnt) return;

    int tid = threadIdx.x, lane = tid & 31, wid = tid >> 5;
    int wm = wid >> 2, wn = wid & 3;   // 4x4 warp grid; warp tile 32(M) x 32(N)

    // ---------- phase 1: h = relu(Xg @ W1^T + b1), K-stage 64 ----------
    int rA = tid >> 2, ch = tid & 3;   // row 0..127, 4 col-chunk pairs
    int tokr = (m0 + rA < cnt) ? (g_tok[e * NTOK + m0 + rA] >> 1) : 0;

    float c[2][4][4];
#pragma unroll
    for (int mi = 0; mi < 2; mi++)
#pragma unroll
        for (int ni = 0; ni < 4; ni++)
#pragma unroll
            for (int q = 0; q < 4; q++) c[mi][ni][q] = 0.f;

    const int NK = HD / 64;  // 32

    // per stage: A row has 8 chunks of 8 halves; thread does chunks {ch, ch+4} for A and B
#define FM_LOAD(s, k0)                                                                          \
    do {                                                                                        \
        __nv_bfloat16* _a = &As[s][0][0];                                                       \
        __nv_bfloat16* _b = _a + 128 * 72 * (3) - 128 * 72 * 3 + 0; (void)_b;                   \
        _Pragma("unroll")                                                                       \
        for (int q = 0; q < 2; q++) {                                                           \
            int cc = (ch + q * 4) * 8;                                                          \
            CP16(smem_u32(&As[s][0][0] + (size_t)rA * 72 + cc),                                 \
                 g_xb + (size_t)tokr * HD + (k0) + cc);                                         \
            CP16(smem_u32(&As[s][0][0] + (size_t)(128 * 72) * 3 / 3 * 0 + 0) +                  \
                     (128 * 72 * 2) * 0, g_xb);                                                 \
        }                                                                                       \
    } while (0)
#undef FM_LOAD

    // cleaner: B stages live directly after the 3 A stages? No — interleave A/B per stage:
    // stage s occupies [s*36864, s*36864+18432) = A, [s*36864+18432, (s+1)*36864) = B
#define P1A(s) ((__nv_bfloat16*)(sm + (s) * 36864))
#define P1B(s) ((__nv_bfloat16*)(sm + (s) * 36864 + 18432))
#define FM_LOAD(s, k0)                                                                          \
    do {                                                                                        \
        _Pragma("unroll")                                                                       \
        for (int q = 0; q < 2; q++) {                                                           \
            int cc = (ch + q * 4) * 8;                                                          \
            CP16(smem_u32(P1A(s) + (size_t)rA * 72 + cc),                                       \
                 g_xb + (size_t)tokr * HD + (k0) + cc);                                         \
            CP16(smem_u32(P1B(s) + (size_t)rA * 72 + cc),                                       \
                 g_w1b + ((size_t)e * BD + rA) * HD + (k0) + cc);                               \
        }                                                                                       \
    } while (0)

    FM_LOAD(0, 0);
    CP_COMMIT();
    FM_LOAD(1, 64);
    CP_COMMIT();

    for (int it = 0; it < NK; it++) {
        CP_WAIT(1);
        __syncthreads();
        if (it + 2 < NK) { FM_LOAD((it + 2) % 3, (it + 2) * 64); }
        CP_COMMIT();

        int s = it % 3;
#pragma unroll
        for (int kk = 0; kk < 4; kk++) {
            uint32_t a[2][4];
#pragma unroll
            for (int mi = 0; mi < 2; mi++) {
                uint32_t ad = smem_u32(P1A(s) + (size_t)(wm * 32 + mi * 16 + (lane & 15)) * 72 +
                                       kk * 16 + ((lane >> 4) << 3));
                ldm4(a[mi][0], a[mi][1], a[mi][2], a[mi][3], ad);
            }
            uint32_t b[4][2];
#pragma unroll
            for (int nj = 0; nj < 2; nj++) {
                uint32_t ad = smem_u32(P1B(s) +
                                       (size_t)(wn * 32 + nj * 16 + (lane & 7) + ((lane >> 4) << 3)) * 72 +
                                       kk * 16 + (((lane >> 3) & 1) << 3));
                uint32_t r0, r1, r2, r3;
                ldm4(r0, r1, r2, r3, ad);
                b[2 * nj][0] = r0; b[2 * nj][1] = r1;
                b[2 * nj + 1][0] = r2; b[2 * nj + 1][1] = r3;
            }
#pragma unroll
            for (int mi = 0; mi < 2; mi++)
#pragma unroll
                for (int ni = 0; ni < 4; ni++) mma16816(c[mi][ni], a[mi], b[ni]);
        }
    }

    __syncthreads();

    // start W2 chunk-0 load
    int r2 = tid >> 2;
#pragma unroll
    for (int q = 0; q < 4; q++) {
        int col = ((tid & 3) * 4 + q) * 8;
        CP16(smem_u32(&W2s[0][r2][col]), g_w2b + ((size_t)e * HD + r2) * BD + col);
    }
    CP_COMMIT();

    // stage h into smem H
    const float* b1e = b1 + e * BD;
#pragma unroll
    for (int mi = 0; mi < 2; mi++) {
#pragma unroll
        for (int rr = 0; rr < 2; rr++) {
            int lr = wm * 32 + mi * 16 + (lane >> 2) + rr * 8;
#pragma unroll
            for (int ni = 0; ni < 4; ni++) {
                int col = wn * 32 + ni * 8 + (lane & 3) * 2;
                float v0 = fmaxf(c[mi][ni][rr * 2 + 0] + b1e[col], 0.f);
                float v1 = fmaxf(c[mi][ni][rr * 2 + 1] + b1e[col + 1], 0.f);
                __nv_bfloat162 pk;
                pk.x = __float2bfloat16(v0);
                pk.y = __float2bfloat16(v1);
                *(__nv_bfloat162*)(&H[lr][col]) = pk;
            }
        }
    }

    if (tid < 128) {
        int gr = m0 + tid;
        int v = (gr < cnt) ? g_tok[e * NTOK + gr] : 0;
        vrow[tid] = v;
        wrow[tid] = (gr < cnt) ? g_w[(v >> 1) * NE + e] : 0.f;
    }
    for (int i = tid; i < HD; i += 512) b2s[i] = b2[(size_t)e * HD + i];

    int lim = cnt - m0;

    // ---------- phase 2: 16 output chunks of 128 cols ----------
    for (int ci = 0; ci < 16; ci++) {
        CP_WAIT(0);
        __syncthreads();
        if (ci < 15) {
#pragma unroll
            for (int q = 0; q < 4; q++) {
                int col = ((tid & 3) * 4 + q) * 8;
                CP16(smem_u32(&W2s[(ci + 1) & 1][r2][col]),
                     g_w2b + ((size_t)e * HD + (ci + 1) * 128 + r2) * BD + col);
            }
            CP_COMMIT();
        }

        int sb = ci & 1;
#pragma unroll
        for (int mi = 0; mi < 2; mi++)
#pragma unroll
            for (int ni = 0; ni < 4; ni++)
#pragma unroll
                for (int q = 0; q < 4; q++) c[mi][ni][q] = 0.f;

#pragma unroll
        for (int kk = 0; kk < 8; kk++) {
            uint32_t a[2][4];
#pragma unroll
            for (int mi = 0; mi < 2; mi++) {
                uint32_t ad = smem_u32(&H[wm * 32 + mi * 16 + (lane & 15)][kk * 16 + ((lane >> 4) << 3)]);
                ldm4(a[mi][0], a[mi][1], a[mi][2], a[mi][3], ad);
            }
            uint32_t b[4][2];
#pragma unroll
            for (int nj = 0; nj < 2; nj++) {
                uint32_t ad = smem_u32(&W2s[sb][wn * 32 + nj * 16 + (lane & 7) + ((lane >> 4) << 3)]
                                          [kk * 16 + (((lane >> 3) & 1) << 3)]);
                uint32_t r0, r1, r2v, r3;
                ldm4(r0, r1, r2v, r3, ad);
                b[2 * nj][0] = r0; b[2 * nj][1] = r1;
                b[2 * nj + 1][0] = r2v; b[2 * nj + 1][1] = r3;
            }
#pragma unroll
            for (int mi = 0; mi < 2; mi++)
#pragma unroll
                for (int ni = 0; ni < 4; ni++) mma16816(c[mi][ni], a[mi], b[ni]);
        }

        __syncthreads();
#pragma unroll
        for (int mi = 0; mi < 2; mi++) {
#pragma unroll
            for (int rr = 0; rr < 2; rr++) {
                int lr = wm * 32 + mi * 16 + (lane >> 2) + rr * 8;
                float wv = wrow[lr];
#pragma unroll
                for (int ni = 0; ni < 4; ni++) {
                    int col = wn * 32 + ni * 8 + (lane & 3) * 2;
                    float v0 = wv * (c[mi][ni][rr * 2 + 0] + b2s[ci * 128 + col]);
                    float v1 = wv * (c[mi][ni][rr * 2 + 1] + b2s[ci * 128 + col + 1]);
                    __nv_bfloat162 pk;
                    pk.x = __float2bfloat16(v0);
                    pk.y = __float2bfloat16(v1);
                    *(__nv_bfloat162*)(&W2s[sb][lr][col]) = pk;
                }
            }
        }
        __syncthreads();

        for (int i = tid; i < 2048; i += 512) {
            int rr2 = i >> 4, cc = (i & 15) << 3;
            if (rr2 < lim) {
                int v = vrow[rr2];
                uint4 val = *(const uint4*)(&W2s[sb][rr2][cc]);
                *(uint4*)(g_scr + (size_t)v * HD + ci * 128 + cc) = val;
            }
        }
    }
}

// ---------------- kernel: combine ----------------
__global__ __launch_bounds__(256) void k_combine(const float* __restrict__ x, float* __restrict__ out) {
    int n = blockIdx.x;
    int tid = threadIdx.x;
    const float4* xr = (const float4*)(x + (size_t)n * HD);
    float4* o = (float4*)(out + (size_t)n * HD);
    const __nv_bfloat162* s0 = (const __nv_bfloat162*)(g_scr + (size_t)(2 * n) * HD);
    const __nv_bfloat162* s1 = (const __nv_bfloat162*)(g_scr + (size_t)(2 * n + 1) * HD);
#pragma unroll
    for (int j = tid; j < HD / 4; j += 256) {
        float4 a = xr[j];
        __nv_bfloat162 p0 = s0[2 * j], p1 = s0[2 * j + 1];
        __nv_bfloat162 q0 = s1[2 * j], q1 = s1[2 * j + 1];
        float4 r;
        r.x = a.x + __bfloat162float(p0.x) + __bfloat162float(q0.x);
        r.y = a.y + __bfloat162float(p0.y) + __bfloat162float(q0.y);
        r.z = a.z + __bfloat162float(p1.x) + __bfloat162float(q1.x);
        r.w = a.w + __bfloat162float(p1.y) + __bfloat162float(q1.y);
        o[j] = r;
    }
}

// ---------------- kernel: aux loss (partials reduce) ----------------
__global__ void k_aux(float* __restrict__ out, int out_size) {
    if (out_size <= NTOK * HD) return;
    __shared__ float red[256];
    __shared__ float auxs;
    int tid = threadIdx.x;
    if (tid == 0) auxs = 0.f;
    float acc[NE];
#pragma unroll
    for (int e = 0; e < NE; e++) acc[e] = 0.f;
    for (int i = tid; i < NTOK / RT; i += 256) {
#pragma unroll
        for (int e = 0; e < NE; e++) acc[e] += g_pp[i * NE + e];
    }
    __syncthreads();
    for (int e = 0; e < NE; e++) {
        red[tid] = acc[e];
        __syncthreads();
        for (int s = 128; s > 0; s >>= 1) {
            if (tid < s) red[tid] += red[tid + s];
            __syncthreads();
        }
        if (tid == 0) {
            float mp = red[0] / (float)NTOK;
            float mf = (float)g_cnt[e] / (float)NTOK;
            auxs += mp * mf;
        }
        __syncthreads();
    }
    if (tid == 0) out[(size_t)NTOK * HD] = auxs * (float)NE;
}

// ---------------- launch ----------------
extern "C" void kernel_launch(void* const* d_in, const int* in_sizes, int n_in,
                              void* d_out, int out_size) {
    const float* x     = (const float*)d_in[0];
    const float* skin  = (const float*)d_in[1];
    const float* Wimg  = (const float*)d_in[2];
    const float* Wskin = (const float*)d_in[3];
    const float* W1    = (const float*)d_in[4];
    const float* b1    = (const float*)d_in[5];
    const float* W2    = (const float*)d_in[6];
    const float* b2    = (const float*)d_in[7];
    float* out = (float*)d_out;

    cudaFuncSetAttribute(k_moe, cudaFuncAttributeMaxDynamicSharedMemorySize, FM_SMEM);

    k_convert<<<2048, 256>>>(W1, W2);
    k_nopA<<<1, 32>>>();
    k_nopB<<<1, 32>>>();
    k_router<<<NTOK / RT, 512>>>(x, skin, Wimg, Wskin);   // 4th launch -> ncu slot
    k_moe<<<dim3(NTOK / 128, NE), 512, FM_SMEM>>>(b1, b2);
    k_combine<<<NTOK, 256>>>(x, out);
    k_aux<<<1, 256>>>(out, out_size);
}

// round 16
// speedup vs baseline: 1.0287x; 1.0287x over previous
#include <cuda_runtime.h>
#include <cuda_bf16.h>
#include <cstdint>

#define NTOK 16384
#define HD   2048
#define NE   8
#define BD   128
#define EPSF 1e-6f

// ---------------- static device scratch ----------------
__device__ __nv_bfloat16 g_xb [NTOK * HD];
__device__ __nv_bfloat16 g_w1b[NE * BD * HD];
__device__ __nv_bfloat16 g_w2b[NE * HD * BD];
__device__ __nv_bfloat16 g_scr[2 * NTOK * HD];
__device__ float g_w   [NTOK * NE];
__device__ float g_pp  [(NTOK / 8) * NE];
__device__ int   g_tok [NE * NTOK];
__device__ int   g_cnt [NE];

// ---------------- helpers ----------------
static __device__ __forceinline__ uint32_t smem_u32(const void* p) {
    return (uint32_t)__cvta_generic_to_shared(p);
}
#define CP16(dst_u32, src_ptr) \
    asm volatile("cp.async.cg.shared.global [%0], [%1], 16;\n" :: "r"(dst_u32), "l"(src_ptr))
#define CP_COMMIT() asm volatile("cp.async.commit_group;\n" ::)
#define CP_WAIT(n)  asm volatile("cp.async.wait_group %0;\n" :: "n"(n))

static __device__ __forceinline__ void ldm4(uint32_t& r0, uint32_t& r1, uint32_t& r2, uint32_t& r3,
                                            uint32_t addr) {
    asm volatile("ldmatrix.sync.aligned.m8n8.x4.shared.b16 {%0,%1,%2,%3}, [%4];"
                 : "=r"(r0), "=r"(r1), "=r"(r2), "=r"(r3) : "r"(addr));
}
static __device__ __forceinline__ void mma16816(float* c, const uint32_t* a, const uint32_t* b) {
    asm volatile(
        "mma.sync.aligned.m16n8k16.row.col.f32.bf16.bf16.f32 "
        "{%0,%1,%2,%3}, {%4,%5,%6,%7}, {%8,%9}, {%0,%1,%2,%3};"
        : "+f"(c[0]), "+f"(c[1]), "+f"(c[2]), "+f"(c[3])
        : "r"(a[0]), "r"(a[1]), "r"(a[2]), "r"(a[3]), "r"(b[0]), "r"(b[1]));
}
// packed fp32x2 math
static __device__ __forceinline__ unsigned long long f2mul(unsigned long long a, unsigned long long b) {
    unsigned long long d;
    asm("mul.rn.f32x2 %0, %1, %2;" : "=l"(d) : "l"(a), "l"(b));
    return d;
}
static __device__ __forceinline__ unsigned long long f2fma(unsigned long long a, unsigned long long b,
                                                           unsigned long long c) {
    unsigned long long d;
    asm("fma.rn.f32x2 %0, %1, %2, %3;" : "=l"(d) : "l"(a), "l"(b), "l"(c));
    return d;
}

// ---------------- no-op pads (so ncu slot 4 = k_router) ----------------
__global__ void k_nopA() {}
__global__ void k_nopB() {}

// ---------------- kernel: weights -> bf16 (+ counter init) ----------------
__global__ void k_convert(const float* __restrict__ W1, const float* __restrict__ W2) {
    if (blockIdx.x == 0 && threadIdx.x < NE) g_cnt[threadIdx.x] = 0;
    int total = NE * BD * HD;
    for (int i = blockIdx.x * blockDim.x + threadIdx.x; i < total; i += gridDim.x * blockDim.x) {
        g_w1b[i] = __float2bfloat16(W1[i]);
        g_w2b[i] = __float2bfloat16(W2[i]);
    }
}

// ---------------- kernel: router v6 (16 tok/block; single-pass convert+dot) ----------------
#define RT 16
__global__ __launch_bounds__(512, 2) void k_router(const float* __restrict__ x,
                                                   const float* __restrict__ skin,
                                                   const float* __restrict__ Wimg,
                                                   const float* __restrict__ Wskin) {
    int nb = blockIdx.x * RT;
    int tid = threadIdx.x, lane = tid & 31, wid = tid >> 5;
    int eg = wid >> 3;   // expert group: experts [eg*4, eg*4+4)
    int wc = wid & 7;    // column chunk: cols [wc*256, wc*256+256)

    __shared__ float part[16][RT][4];
    __shared__ float lg[RT][NE];
    __shared__ float sp[RT][NE];
    __shared__ int   sel[2][RT];

    // this warp's W_img chunk: 4 experts x 8 cols per lane (f32x2 pairs)
    int base = wc * 256 + lane * 8;
    ulonglong2 w0[4], w1[4];
#pragma unroll
    for (int je = 0; je < 4; je++) {
        int e = eg * 4 + je;
        w0[je] = *(const ulonglong2*)(Wimg + (size_t)e * HD + base);
        w1[je] = *(const ulonglong2*)(Wimg + (size_t)e * HD + base + 4);
    }

    // per-token: load x once; convert+store bf16 (eg==0 warps); dot for 4 experts
    for (int t = 0; t < RT; t++) {
        const ulonglong2* xr = (const ulonglong2*)(x + (size_t)(nb + t) * HD + base);
        ulonglong2 a0 = xr[0];
        ulonglong2 a1 = xr[1];

        if (eg == 0) {
            float f0, f1, f2, f3, f4, f5, f6, f7;
            asm("mov.b64 {%0,%1}, %2;" : "=f"(f0), "=f"(f1) : "l"(a0.x));
            asm("mov.b64 {%0,%1}, %2;" : "=f"(f2), "=f"(f3) : "l"(a0.y));
            asm("mov.b64 {%0,%1}, %2;" : "=f"(f4), "=f"(f5) : "l"(a1.x));
            asm("mov.b64 {%0,%1}, %2;" : "=f"(f6), "=f"(f7) : "l"(a1.y));
            uint4 st;
            asm("cvt.rn.bf16x2.f32 %0, %1, %2;" : "=r"(st.x) : "f"(f1), "f"(f0));
            asm("cvt.rn.bf16x2.f32 %0, %1, %2;" : "=r"(st.y) : "f"(f3), "f"(f2));
            asm("cvt.rn.bf16x2.f32 %0, %1, %2;" : "=r"(st.z) : "f"(f5), "f"(f4));
            asm("cvt.rn.bf16x2.f32 %0, %1, %2;" : "=r"(st.w) : "f"(f7), "f"(f6));
            *(uint4*)(g_xb + (size_t)(nb + t) * HD + base) = st;
        }

        float v[4];
#pragma unroll
        for (int je = 0; je < 4; je++) {
            unsigned long long acc = f2mul(a0.x, w0[je].x);
            acc = f2fma(a0.y, w0[je].y, acc);
            acc = f2fma(a1.x, w1[je].x, acc);
            acc = f2fma(a1.y, w1[je].y, acc);
            float flo, fhi;
            asm("mov.b64 {%0, %1}, %2;" : "=f"(flo), "=f"(fhi) : "l"(acc));
            v[je] = flo + fhi;
        }
        {
            int bit = lane & 1;
            float s0 = __shfl_xor_sync(0xffffffffu, bit ? v[0] : v[2], 1);
            float s1 = __shfl_xor_sync(0xffffffffu, bit ? v[1] : v[3], 1);
            v[0] = (bit ? v[2] : v[0]) + s0;
            v[1] = (bit ? v[3] : v[1]) + s1;
        }
        {
            int bit = (lane >> 1) & 1;
            float s0 = __shfl_xor_sync(0xffffffffu, bit ? v[0] : v[1], 2);
            v[0] = (bit ? v[1] : v[0]) + s0;
        }
        v[0] += __shfl_xor_sync(0xffffffffu, v[0], 4);
        v[0] += __shfl_xor_sync(0xffffffffu, v[0], 8);
        v[0] += __shfl_xor_sync(0xffffffffu, v[0], 16);
        if (lane < 4) {
            int je = ((lane & 1) << 1) | ((lane >> 1) & 1);
            part[wid][t][je] = v[0];
        }
    }
    __syncthreads();

    // cross-warp combine + skin term
    if (tid < RT * NE) {
        int t = tid >> 3, e = tid & 7;
        int eg2 = e >> 2, je = e & 3;
        float s = 0.f;
#pragma unroll
        for (int w = 0; w < 8; w++) s += part[eg2 * 8 + w][t][je];
        int n = nb + t;
        s += skin[n * 3 + 0] * Wskin[e * 3 + 0] +
             skin[n * 3 + 1] * Wskin[e * 3 + 1] +
             skin[n * 3 + 2] * Wskin[e * 3 + 2];
        lg[t][e] = s;
    }
    __syncthreads();

    // softmax + top-2 per token
    if (tid < RT) {
        int t = tid, n = nb + t;
        float p[NE];
        float mx = lg[t][0];
#pragma unroll
        for (int e = 1; e < NE; e++) mx = fmaxf(mx, lg[t][e]);
        float ssum = 0.f;
#pragma unroll
        for (int e = 0; e < NE; e++) { p[e] = expf(lg[t][e] - mx); ssum += p[e]; }
        float inv = 1.f / ssum;
#pragma unroll
        for (int e = 0; e < NE; e++) p[e] *= inv;

        int i1 = 0;
#pragma unroll
        for (int e = 1; e < NE; e++) if (p[e] > p[i1]) i1 = e;
        int i2 = (i1 == 0) ? 1 : 0;
#pragma unroll
        for (int e = 0; e < NE; e++) { if (e != i1 && p[e] > p[i2]) i2 = e; }

        float v1 = p[i1], v2 = p[i2];
        float wn = 1.f / (v1 + v2 + EPSF);
        float wv[NE];
#pragma unroll
        for (int e = 0; e < NE; e++) wv[e] = 0.f;
        wv[i1] = v1 * wn;
        wv[i2] = v2 * wn;
#pragma unroll
        for (int e = 0; e < NE; e++) { g_w[n * NE + e] = wv[e]; sp[t][e] = p[e]; }

        sel[0][t] = i1;
        sel[1][t] = i2;
    }
    __syncthreads();

    // per-expert scatter: one independent atomic per (block, expert)
    if (tid < NE) {
        int e = tid;
        int cnt = 0;
#pragma unroll
        for (int t = 0; t < RT; t++) cnt += (sel[0][t] == e) + (sel[1][t] == e);
        if (cnt) {
            int bse = atomicAdd(&g_cnt[e], cnt);
            int o = 0;
#pragma unroll
            for (int t = 0; t < RT; t++) {
                if (sel[0][t] == e) g_tok[e * NTOK + bse + (o++)] = (nb + t) * 2;
                if (sel[1][t] == e) g_tok[e * NTOK + bse + (o++)] = (nb + t) * 2 + 1;
            }
        }
    }

    // per-block prob partials for aux loss (deterministic)
    if (tid >= 32 && tid < 32 + NE) {
        int e = tid - 32;
        float s = 0.f;
#pragma unroll
        for (int t = 0; t < RT; t++) s += sp[t][e];
        g_pp[blockIdx.x * NE + e] = s;
    }
}

// ---------------- kernel: fused MoE expert, 512 threads, warp tile 32x32 (R12/R14 version) ----------------
#define FM_SMEM 112640
__global__ __launch_bounds__(512, 2) void k_moe(const float* __restrict__ b1,
                                                const float* __restrict__ b2) {
    extern __shared__ __align__(16) char sm[];
    __nv_bfloat16 (*As)[128][40] = (__nv_bfloat16 (*)[128][40])sm;
    __nv_bfloat16 (*Bs)[128][40] = (__nv_bfloat16 (*)[128][40])(sm + 40960);
    __nv_bfloat16 (*H)[136]       = (__nv_bfloat16 (*)[136])sm;
    __nv_bfloat16 (*W2s)[128][136] = (__nv_bfloat16 (*)[128][136])(sm + 34816);
    float* b2s = (float*)(sm + 104448);

    __shared__ int   vrow[128];
    __shared__ float wrow[128];

    int e = blockIdx.y;
    int cnt = g_cnt[e];
    int m0 = blockIdx.x * 128;
    if (m0 >= cnt) return;

    int tid = threadIdx.x, lane = tid & 31, wid = tid >> 5;
    int wm = wid >> 2, wn = wid & 3;   // 4x4 warp grid; warp tile 32(M) x 32(N)

    // ---------- phase 1: h = relu(Xg @ W1^T + b1) ----------
    int rA = tid >> 2, ch = tid & 3;
    int tokr = (m0 + rA < cnt) ? (g_tok[e * NTOK + m0 + rA] >> 1) : 0;

    float c[2][4][4];
#pragma unroll
    for (int mi = 0; mi < 2; mi++)
#pragma unroll
        for (int ni = 0; ni < 4; ni++)
#pragma unroll
            for (int q = 0; q < 4; q++) c[mi][ni][q] = 0.f;

    const int NK = HD / 32;  // 64

#define FM_LOAD(s, k0)                                                                        \
    do {                                                                                      \
        CP16(smem_u32(&As[s][rA][ch * 8]), g_xb + (size_t)tokr * HD + (k0) + ch * 8);         \
        CP16(smem_u32(&Bs[s][rA][ch * 8]), g_w1b + ((size_t)e * BD + rA) * HD + (k0) + ch * 8); \
    } while (0)

#pragma unroll
    for (int s = 0; s < 3; s++) { FM_LOAD(s, s * 32); CP_COMMIT(); }

    for (int it = 0; it < NK; it++) {
        CP_WAIT(2);
        __syncthreads();
        int pf = it + 3;
        if (pf < NK) FM_LOAD(pf & 3, pf * 32);
        CP_COMMIT();

        int s = it & 3;
#pragma unroll
        for (int kk = 0; kk < 2; kk++) {
            uint32_t a[2][4];
#pragma unroll
            for (int mi = 0; mi < 2; mi++) {
                uint32_t ad = smem_u32(&As[s][wm * 32 + mi * 16 + (lane & 15)][kk * 16 + ((lane >> 4) << 3)]);
                ldm4(a[mi][0], a[mi][1], a[mi][2], a[mi][3], ad);
            }
            uint32_t b[4][2];
#pragma unroll
            for (int nj = 0; nj < 2; nj++) {
                uint32_t ad = smem_u32(&Bs[s][wn * 32 + nj * 16 + (lane & 7) + ((lane >> 4) << 3)]
                                          [kk * 16 + (((lane >> 3) & 1) << 3)]);
                uint32_t r0, r1, r2, r3;
                ldm4(r0, r1, r2, r3, ad);
                b[2 * nj][0] = r0; b[2 * nj][1] = r1;
                b[2 * nj + 1][0] = r2; b[2 * nj + 1][1] = r3;
            }
#pragma unroll
            for (int mi = 0; mi < 2; mi++)
#pragma unroll
                for (int ni = 0; ni < 4; ni++) mma16816(c[mi][ni], a[mi], b[ni]);
        }
    }

    __syncthreads();

    // start W2 chunk-0 load
    int r2 = tid >> 2;
#pragma unroll
    for (int q = 0; q < 4; q++) {
        int col = ((tid & 3) * 4 + q) * 8;
        CP16(smem_u32(&W2s[0][r2][col]), g_w2b + ((size_t)e * HD + r2) * BD + col);
    }
    CP_COMMIT();

    // stage h into smem H
    const float* b1e = b1 + e * BD;
#pragma unroll
    for (int mi = 0; mi < 2; mi++) {
#pragma unroll
        for (int rr = 0; rr < 2; rr++) {
            int lr = wm * 32 + mi * 16 + (lane >> 2) + rr * 8;
#pragma unroll
            for (int ni = 0; ni < 4; ni++) {
                int col = wn * 32 + ni * 8 + (lane & 3) * 2;
                float v0 = fmaxf(c[mi][ni][rr * 2 + 0] + b1e[col], 0.f);
                float v1 = fmaxf(c[mi][ni][rr * 2 + 1] + b1e[col + 1], 0.f);
                __nv_bfloat162 pk;
                pk.x = __float2bfloat16(v0);
                pk.y = __float2bfloat16(v1);
                *(__nv_bfloat162*)(&H[lr][col]) = pk;
            }
        }
    }

    if (tid < 128) {
        int gr = m0 + tid;
        int v = (gr < cnt) ? g_tok[e * NTOK + gr] : 0;
        vrow[tid] = v;
        wrow[tid] = (gr < cnt) ? g_w[(v >> 1) * NE + e] : 0.f;
    }
    for (int i = tid; i < HD; i += 512) b2s[i] = b2[(size_t)e * HD + i];

    int lim = cnt - m0;

    // ---------- phase 2: 16 output chunks of 128 cols ----------
    for (int ci = 0; ci < 16; ci++) {
        CP_WAIT(0);
        __syncthreads();
        if (ci < 15) {
#pragma unroll
            for (int q = 0; q < 4; q++) {
                int col = ((tid & 3) * 4 + q) * 8;
                CP16(smem_u32(&W2s[(ci + 1) & 1][r2][col]),
                     g_w2b + ((size_t)e * HD + (ci + 1) * 128 + r2) * BD + col);
            }
            CP_COMMIT();
        }

        int sb = ci & 1;
#pragma unroll
        for (int mi = 0; mi < 2; mi++)
#pragma unroll
            for (int ni = 0; ni < 4; ni++)
#pragma unroll
                for (int q = 0; q < 4; q++) c[mi][ni][q] = 0.f;

#pragma unroll
        for (int kk = 0; kk < 8; kk++) {
            uint32_t a[2][4];
#pragma unroll
            for (int mi = 0; mi < 2; mi++) {
                uint32_t ad = smem_u32(&H[wm * 32 + mi * 16 + (lane & 15)][kk * 16 + ((lane >> 4) << 3)]);
                ldm4(a[mi][0], a[mi][1], a[mi][2], a[mi][3], ad);
            }
            uint32_t b[4][2];
#pragma unroll
            for (int nj = 0; nj < 2; nj++) {
                uint32_t ad = smem_u32(&W2s[sb][wn * 32 + nj * 16 + (lane & 7) + ((lane >> 4) << 3)]
                                          [kk * 16 + (((lane >> 3) & 1) << 3)]);
                uint32_t r0, r1, r2v, r3;
                ldm4(r0, r1, r2v, r3, ad);
                b[2 * nj][0] = r0; b[2 * nj][1] = r1;
                b[2 * nj + 1][0] = r2v; b[2 * nj + 1][1] = r3;
            }
#pragma unroll
            for (int mi = 0; mi < 2; mi++)
#pragma unroll
                for (int ni = 0; ni < 4; ni++) mma16816(c[mi][ni], a[mi], b[ni]);
        }

        __syncthreads();
#pragma unroll
        for (int mi = 0; mi < 2; mi++) {
#pragma unroll
            for (int rr = 0; rr < 2; rr++) {
                int lr = wm * 32 + mi * 16 + (lane >> 2) + rr * 8;
                float wv = wrow[lr];
#pragma unroll
                for (int ni = 0; ni < 4; ni++) {
                    int col = wn * 32 + ni * 8 + (lane & 3) * 2;
                    float v0 = wv * (c[mi][ni][rr * 2 + 0] + b2s[ci * 128 + col]);
                    float v1 = wv * (c[mi][ni][rr * 2 + 1] + b2s[ci * 128 + col + 1]);
                    __nv_bfloat162 pk;
                    pk.x = __float2bfloat16(v0);
                    pk.y = __float2bfloat16(v1);
                    *(__nv_bfloat162*)(&W2s[sb][lr][col]) = pk;
                }
            }
        }
        __syncthreads();

        for (int i = tid; i < 2048; i += 512) {
            int rr2 = i >> 4, cc = (i & 15) << 3;
            if (rr2 < lim) {
                int v = vrow[rr2];
                uint4 val = *(const uint4*)(&W2s[sb][rr2][cc]);
                *(uint4*)(g_scr + (size_t)v * HD + ci * 128 + cc) = val;
            }
        }
    }
}

// ---------------- kernel: combine ----------------
__global__ __launch_bounds__(256) void k_combine(const float* __restrict__ x, float* __restrict__ out) {
    int n = blockIdx.x;
    int tid = threadIdx.x;
    const float4* xr = (const float4*)(x + (size_t)n * HD);
    float4* o = (float4*)(out + (size_t)n * HD);
    const __nv_bfloat162* s0 = (const __nv_bfloat162*)(g_scr + (size_t)(2 * n) * HD);
    const __nv_bfloat162* s1 = (const __nv_bfloat162*)(g_scr + (size_t)(2 * n + 1) * HD);
#pragma unroll
    for (int j = tid; j < HD / 4; j += 256) {
        float4 a = xr[j];
        __nv_bfloat162 p0 = s0[2 * j], p1 = s0[2 * j + 1];
        __nv_bfloat162 q0 = s1[2 * j], q1 = s1[2 * j + 1];
        float4 r;
        r.x = a.x + __bfloat162float(p0.x) + __bfloat162float(q0.x);
        r.y = a.y + __bfloat162float(p0.y) + __bfloat162float(q0.y);
        r.z = a.z + __bfloat162float(p1.x) + __bfloat162float(q1.x);
        r.w = a.w + __bfloat162float(p1.y) + __bfloat162float(q1.y);
        o[j] = r;
    }
}

// ---------------- kernel: aux loss (partials reduce) ----------------
__global__ void k_aux(float* __restrict__ out, int out_size) {
    if (out_size <= NTOK * HD) return;
    __shared__ float red[256];
    __shared__ float auxs;
    int tid = threadIdx.x;
    if (tid == 0) auxs = 0.f;
    float acc[NE];
#pragma unroll
    for (int e = 0; e < NE; e++) acc[e] = 0.f;
    for (int i = tid; i < NTOK / RT; i += 256) {
#pragma unroll
        for (int e = 0; e < NE; e++) acc[e] += g_pp[i * NE + e];
    }
    __syncthreads();
    for (int e = 0; e < NE; e++) {
        red[tid] = acc[e];
        __syncthreads();
        for (int s = 128; s > 0; s >>= 1) {
            if (tid < s) red[tid] += red[tid + s];
            __syncthreads();
        }
        if (tid == 0) {
            float mp = red[0] / (float)NTOK;
            float mf = (float)g_cnt[e] / (float)NTOK;
            auxs += mp * mf;
        }
        __syncthreads();
    }
    if (tid == 0) out[(size_t)NTOK * HD] = auxs * (float)NE;
}

// ---------------- launch ----------------
extern "C" void kernel_launch(void* const* d_in, const int* in_sizes, int n_in,
                              void* d_out, int out_size) {
    const float* x     = (const float*)d_in[0];
    const float* skin  = (const float*)d_in[1];
    const float* Wimg  = (const float*)d_in[2];
    const float* Wskin = (const float*)d_in[3];
    const float* W1    = (const float*)d_in[4];
    const float* b1    = (const float*)d_in[5];
    const float* W2    = (const float*)d_in[6];
    const float* b2    = (const float*)d_in[7];
    float* out = (float*)d_out;

    cudaFuncSetAttribute(k_moe, cudaFuncAttributeMaxDynamicSharedMemorySize, FM_SMEM);

    k_convert<<<2048, 256>>>(W1, W2);
    k_nopA<<<1, 32>>>();
    k_nopB<<<1, 32>>>();
    k_router<<<NTOK / RT, 512>>>(x, skin, Wimg, Wskin);   // 4th launch -> ncu slot
    k_moe<<<dim3(NTOK / 128, NE), 512, FM_SMEM>>>(b1, b2);
    k_combine<<<NTOK, 256>>>(x, out);
    k_aux<<<1, 256>>>(out, out_size);
}

// round 17
// speedup vs baseline: 1.0809x; 1.0508x over previous
#include <cuda_runtime.h>
#include <cuda_bf16.h>
#include <cstdint>

#define NTOK 16384
#define HD   2048
#define NE   8
#define BD   128
#define EPSF 1e-6f

// ---------------- static device scratch ----------------
__device__ __nv_bfloat16 g_xb [NTOK * HD];
__device__ __nv_bfloat16 g_w1b[NE * BD * HD];
__device__ __nv_bfloat16 g_w2b[NE * HD * BD];
__device__ __nv_bfloat16 g_scr[2 * NTOK * HD];
__device__ float g_w   [NTOK * NE];
__device__ float g_pp  [(NTOK / 8) * NE];
__device__ int   g_tok [NE * NTOK];
__device__ int   g_cnt [NE];

// ---------------- helpers ----------------
static __device__ __forceinline__ uint32_t smem_u32(const void* p) {
    return (uint32_t)__cvta_generic_to_shared(p);
}
#define CP16(dst_u32, src_ptr) \
    asm volatile("cp.async.cg.shared.global [%0], [%1], 16;\n" :: "r"(dst_u32), "l"(src_ptr))
#define CP_COMMIT() asm volatile("cp.async.commit_group;\n" ::)
#define CP_WAIT(n)  asm volatile("cp.async.wait_group %0;\n" :: "n"(n))

static __device__ __forceinline__ void ldm4(uint32_t& r0, uint32_t& r1, uint32_t& r2, uint32_t& r3,
                                            uint32_t addr) {
    asm volatile("ldmatrix.sync.aligned.m8n8.x4.shared.b16 {%0,%1,%2,%3}, [%4];"
                 : "=r"(r0), "=r"(r1), "=r"(r2), "=r"(r3) : "r"(addr));
}
static __device__ __forceinline__ void mma16816(float* c, const uint32_t* a, const uint32_t* b) {
    asm volatile(
        "mma.sync.aligned.m16n8k16.row.col.f32.bf16.bf16.f32 "
        "{%0,%1,%2,%3}, {%4,%5,%6,%7}, {%8,%9}, {%0,%1,%2,%3};"
        : "+f"(c[0]), "+f"(c[1]), "+f"(c[2]), "+f"(c[3])
        : "r"(a[0]), "r"(a[1]), "r"(a[2]), "r"(a[3]), "r"(b[0]), "r"(b[1]));
}
// packed fp32x2 math
static __device__ __forceinline__ unsigned long long f2mul(unsigned long long a, unsigned long long b) {
    unsigned long long d;
    asm("mul.rn.f32x2 %0, %1, %2;" : "=l"(d) : "l"(a), "l"(b));
    return d;
}
static __device__ __forceinline__ unsigned long long f2fma(unsigned long long a, unsigned long long b,
                                                           unsigned long long c) {
    unsigned long long d;
    asm("fma.rn.f32x2 %0, %1, %2, %3;" : "=l"(d) : "l"(a), "l"(b), "l"(c));
    return d;
}

// ---------------- kernel: weights -> bf16 (+ counter init) ----------------
__global__ void k_convert(const float* __restrict__ W1, const float* __restrict__ W2) {
    if (blockIdx.x == 0 && threadIdx.x < NE) g_cnt[threadIdx.x] = 0;
    int total = NE * BD * HD;
    for (int i = blockIdx.x * blockDim.x + threadIdx.x; i < total; i += gridDim.x * blockDim.x) {
        g_w1b[i] = __float2bfloat16(W1[i]);
        g_w2b[i] = __float2bfloat16(W2[i]);
    }
}

// ---------------- kernel: router v4 (16 tokens/block; 4 experts/warp; f32x2 FMA) ----------------
#define RT 16
__global__ __launch_bounds__(512, 2) void k_router(const float* __restrict__ x,
                                                   const float* __restrict__ skin,
                                                   const float* __restrict__ Wimg,
                                                   const float* __restrict__ Wskin) {
    int nb = blockIdx.x * RT;
    int tid = threadIdx.x, lane = tid & 31, wid = tid >> 5;
    int eg = wid >> 3;   // expert group: experts [eg*4, eg*4+4)
    int wc = wid & 7;    // column chunk: cols [wc*256, wc*256+256)

    __shared__ float part[16][RT][4];
    __shared__ float lg[RT][NE];
    __shared__ float sp[RT][NE];
    __shared__ int   sel[2][RT];

    // 1) bf16 conversion pass (coalesced; populates caches for the dot pass)
    {
        const float4* xs4 = (const float4*)(x + (size_t)nb * HD);
        uint2* xd = (uint2*)(g_xb + (size_t)nb * HD);
#pragma unroll
        for (int k = 0; k < RT * HD / 4 / 512; k++) {
            int i = tid + k * 512;
            float4 a = xs4[i];
            uint32_t lo, hi;
            asm("cvt.rn.bf16x2.f32 %0, %1, %2;" : "=r"(lo) : "f"(a.y), "f"(a.x));
            asm("cvt.rn.bf16x2.f32 %0, %1, %2;" : "=r"(hi) : "f"(a.w), "f"(a.z));
            xd[i] = make_uint2(lo, hi);
        }
    }

    // 2) this warp's W_img chunk: 4 experts x 8 cols per lane (f32x2 pairs)
    int base = wc * 256 + lane * 8;
    ulonglong2 w0[4], w1[4];
#pragma unroll
    for (int je = 0; je < 4; je++) {
        int e = eg * 4 + je;
        w0[je] = *(const ulonglong2*)(Wimg + (size_t)e * HD + base);
        w1[je] = *(const ulonglong2*)(Wimg + (size_t)e * HD + base + 4);
    }

    // 3) per-token dots (4 experts per warp) + transpose-reduce
    for (int t = 0; t < RT; t++) {
        const ulonglong2* xr = (const ulonglong2*)(x + (size_t)(nb + t) * HD + base);
        ulonglong2 a0 = xr[0];
        ulonglong2 a1 = xr[1];
        float v[4];
#pragma unroll
        for (int je = 0; je < 4; je++) {
            unsigned long long acc = f2mul(a0.x, w0[je].x);
            acc = f2fma(a0.y, w0[je].y, acc);
            acc = f2fma(a1.x, w1[je].x, acc);
            acc = f2fma(a1.y, w1[je].y, acc);
            float flo, fhi;
            asm("mov.b64 {%0, %1}, %2;" : "=f"(flo), "=f"(fhi) : "l"(acc));
            v[je] = flo + fhi;
        }
        {
            int bit = lane & 1;
            float s0 = __shfl_xor_sync(0xffffffffu, bit ? v[0] : v[2], 1);
            float s1 = __shfl_xor_sync(0xffffffffu, bit ? v[1] : v[3], 1);
            v[0] = (bit ? v[2] : v[0]) + s0;
            v[1] = (bit ? v[3] : v[1]) + s1;
        }
        {
            int bit = (lane >> 1) & 1;
            float s0 = __shfl_xor_sync(0xffffffffu, bit ? v[0] : v[1], 2);
            v[0] = (bit ? v[1] : v[0]) + s0;
        }
        v[0] += __shfl_xor_sync(0xffffffffu, v[0], 4);
        v[0] += __shfl_xor_sync(0xffffffffu, v[0], 8);
        v[0] += __shfl_xor_sync(0xffffffffu, v[0], 16);
        if (lane < 4) {
            int je = ((lane & 1) << 1) | ((lane >> 1) & 1);
            part[wid][t][je] = v[0];
        }
    }
    __syncthreads();

    // 4) cross-warp combine + skin term  (RT*NE = 128 threads)
    if (tid < RT * NE) {
        int t = tid >> 3, e = tid & 7;
        int eg2 = e >> 2, je = e & 3;
        float s = 0.f;
#pragma unroll
        for (int w = 0; w < 8; w++) s += part[eg2 * 8 + w][t][je];
        int n = nb + t;
        s += skin[n * 3 + 0] * Wskin[e * 3 + 0] +
             skin[n * 3 + 1] * Wskin[e * 3 + 1] +
             skin[n * 3 + 2] * Wskin[e * 3 + 2];
        lg[t][e] = s;
    }
    __syncthreads();

    // 5) softmax + top-2 per token
    if (tid < RT) {
        int t = tid, n = nb + t;
        float p[NE];
        float mx = lg[t][0];
#pragma unroll
        for (int e = 1; e < NE; e++) mx = fmaxf(mx, lg[t][e]);
        float ssum = 0.f;
#pragma unroll
        for (int e = 0; e < NE; e++) { p[e] = expf(lg[t][e] - mx); ssum += p[e]; }
        float inv = 1.f / ssum;
#pragma unroll
        for (int e = 0; e < NE; e++) p[e] *= inv;

        int i1 = 0;
#pragma unroll
        for (int e = 1; e < NE; e++) if (p[e] > p[i1]) i1 = e;
        int i2 = (i1 == 0) ? 1 : 0;
#pragma unroll
        for (int e = 0; e < NE; e++) { if (e != i1 && p[e] > p[i2]) i2 = e; }

        float v1 = p[i1], v2 = p[i2];
        float wn = 1.f / (v1 + v2 + EPSF);
        float wv[NE];
#pragma unroll
        for (int e = 0; e < NE; e++) wv[e] = 0.f;
        wv[i1] = v1 * wn;
        wv[i2] = v2 * wn;
#pragma unroll
        for (int e = 0; e < NE; e++) { g_w[n * NE + e] = wv[e]; sp[t][e] = p[e]; }

        sel[0][t] = i1;
        sel[1][t] = i2;
    }
    __syncthreads();

    // 6) per-expert scatter: one independent atomic per (block, expert)
    if (tid < NE) {
        int e = tid;
        int cnt = 0;
#pragma unroll
        for (int t = 0; t < RT; t++) cnt += (sel[0][t] == e) + (sel[1][t] == e);
        if (cnt) {
            int bse = atomicAdd(&g_cnt[e], cnt);
            int o = 0;
#pragma unroll
            for (int t = 0; t < RT; t++) {
                if (sel[0][t] == e) g_tok[e * NTOK + bse + (o++)] = (nb + t) * 2;
                if (sel[1][t] == e) g_tok[e * NTOK + bse + (o++)] = (nb + t) * 2 + 1;
            }
        }
    }

    // 7) per-block prob partials for aux loss (deterministic)
    if (tid >= 32 && tid < 32 + NE) {
        int e = tid - 32;
        float s = 0.f;
#pragma unroll
        for (int t = 0; t < RT; t++) s += sp[t][e];
        g_pp[blockIdx.x * NE + e] = s;
    }
}

// ---------------- kernel: fused MoE expert, 512 threads, warp tile 32x32 ----------------
#define FM_SMEM 112640
__global__ __launch_bounds__(512, 2) void k_moe(const float* __restrict__ b1,
                                                const float* __restrict__ b2) {
    extern __shared__ __align__(16) char sm[];
    __nv_bfloat16 (*As)[128][40] = (__nv_bfloat16 (*)[128][40])sm;
    __nv_bfloat16 (*Bs)[128][40] = (__nv_bfloat16 (*)[128][40])(sm + 40960);
    __nv_bfloat16 (*H)[136]       = (__nv_bfloat16 (*)[136])sm;
    __nv_bfloat16 (*W2s)[128][136] = (__nv_bfloat16 (*)[128][136])(sm + 34816);
    float* b2s = (float*)(sm + 104448);

    __shared__ int   vrow[128];
    __shared__ float wrow[128];

    int e = blockIdx.y;
    int cnt = g_cnt[e];
    int m0 = blockIdx.x * 128;
    if (m0 >= cnt) return;

    int tid = threadIdx.x, lane = tid & 31, wid = tid >> 5;
    int wm = wid >> 2, wn = wid & 3;   // 4x4 warp grid; warp tile 32(M) x 32(N)

    // ---------- phase 1: h = relu(Xg @ W1^T + b1) ----------
    int rA = tid >> 2, ch = tid & 3;
    int tokr = (m0 + rA < cnt) ? (g_tok[e * NTOK + m0 + rA] >> 1) : 0;

    float c[2][4][4];
#pragma unroll
    for (int mi = 0; mi < 2; mi++)
#pragma unroll
        for (int ni = 0; ni < 4; ni++)
#pragma unroll
            for (int q = 0; q < 4; q++) c[mi][ni][q] = 0.f;

    const int NK = HD / 32;  // 64

#define FM_LOAD(s, k0)                                                                        \
    do {                                                                                      \
        CP16(smem_u32(&As[s][rA][ch * 8]), g_xb + (size_t)tokr * HD + (k0) + ch * 8);         \
        CP16(smem_u32(&Bs[s][rA][ch * 8]), g_w1b + ((size_t)e * BD + rA) * HD + (k0) + ch * 8); \
    } while (0)

#pragma unroll
    for (int s = 0; s < 3; s++) { FM_LOAD(s, s * 32); CP_COMMIT(); }

    for (int it = 0; it < NK; it++) {
        CP_WAIT(2);
        __syncthreads();
        int pf = it + 3;
        if (pf < NK) FM_LOAD(pf & 3, pf * 32);
        CP_COMMIT();

        int s = it & 3;
#pragma unroll
        for (int kk = 0; kk < 2; kk++) {
            uint32_t a[2][4];
#pragma unroll
            for (int mi = 0; mi < 2; mi++) {
                uint32_t ad = smem_u32(&As[s][wm * 32 + mi * 16 + (lane & 15)][kk * 16 + ((lane >> 4) << 3)]);
                ldm4(a[mi][0], a[mi][1], a[mi][2], a[mi][3], ad);
            }
            uint32_t b[4][2];
#pragma unroll
            for (int nj = 0; nj < 2; nj++) {
                uint32_t ad = smem_u32(&Bs[s][wn * 32 + nj * 16 + (lane & 7) + ((lane >> 4) << 3)]
                                          [kk * 16 + (((lane >> 3) & 1) << 3)]);
                uint32_t r0, r1, r2, r3;
                ldm4(r0, r1, r2, r3, ad);
                b[2 * nj][0] = r0; b[2 * nj][1] = r1;
                b[2 * nj + 1][0] = r2; b[2 * nj + 1][1] = r3;
            }
#pragma unroll
            for (int mi = 0; mi < 2; mi++)
#pragma unroll
                for (int ni = 0; ni < 4; ni++) mma16816(c[mi][ni], a[mi], b[ni]);
        }
    }

    __syncthreads();

    // start W2 chunk-0 load
    int r2 = tid >> 2;
#pragma unroll
    for (int q = 0; q < 4; q++) {
        int col = ((tid & 3) * 4 + q) * 8;
        CP16(smem_u32(&W2s[0][r2][col]), g_w2b + ((size_t)e * HD + r2) * BD + col);
    }
    CP_COMMIT();

    // stage h into smem H
    const float* b1e = b1 + e * BD;
#pragma unroll
    for (int mi = 0; mi < 2; mi++) {
#pragma unroll
        for (int rr = 0; rr < 2; rr++) {
            int lr = wm * 32 + mi * 16 + (lane >> 2) + rr * 8;
#pragma unroll
            for (int ni = 0; ni < 4; ni++) {
                int col = wn * 32 + ni * 8 + (lane & 3) * 2;
                float v0 = fmaxf(c[mi][ni][rr * 2 + 0] + b1e[col], 0.f);
                float v1 = fmaxf(c[mi][ni][rr * 2 + 1] + b1e[col + 1], 0.f);
                __nv_bfloat162 pk;
                pk.x = __float2bfloat16(v0);
                pk.y = __float2bfloat16(v1);
                *(__nv_bfloat162*)(&H[lr][col]) = pk;
            }
        }
    }

    if (tid < 128) {
        int gr = m0 + tid;
        int v = (gr < cnt) ? g_tok[e * NTOK + gr] : 0;
        vrow[tid] = v;
        wrow[tid] = (gr < cnt) ? g_w[(v >> 1) * NE + e] : 0.f;
    }
    for (int i = tid; i < HD; i += 512) b2s[i] = b2[(size_t)e * HD + i];

    int lim = cnt - m0;

    // ---------- phase 2: 16 output chunks of 128 cols ----------
    for (int ci = 0; ci < 16; ci++) {
        CP_WAIT(0);
        __syncthreads();
        if (ci < 15) {
#pragma unroll
            for (int q = 0; q < 4; q++) {
                int col = ((tid & 3) * 4 + q) * 8;
                CP16(smem_u32(&W2s[(ci + 1) & 1][r2][col]),
                     g_w2b + ((size_t)e * HD + (ci + 1) * 128 + r2) * BD + col);
            }
            CP_COMMIT();
        }

        int sb = ci & 1;
#pragma unroll
        for (int mi = 0; mi < 2; mi++)
#pragma unroll
            for (int ni = 0; ni < 4; ni++)
#pragma unroll
                for (int q = 0; q < 4; q++) c[mi][ni][q] = 0.f;

#pragma unroll
        for (int kk = 0; kk < 8; kk++) {
            uint32_t a[2][4];
#pragma unroll
            for (int mi = 0; mi < 2; mi++) {
                uint32_t ad = smem_u32(&H[wm * 32 + mi * 16 + (lane & 15)][kk * 16 + ((lane >> 4) << 3)]);
                ldm4(a[mi][0], a[mi][1], a[mi][2], a[mi][3], ad);
            }
            uint32_t b[4][2];
#pragma unroll
            for (int nj = 0; nj < 2; nj++) {
                uint32_t ad = smem_u32(&W2s[sb][wn * 32 + nj * 16 + (lane & 7) + ((lane >> 4) << 3)]
                                          [kk * 16 + (((lane >> 3) & 1) << 3)]);
                uint32_t r0, r1, r2v, r3;
                ldm4(r0, r1, r2v, r3, ad);
                b[2 * nj][0] = r0; b[2 * nj][1] = r1;
                b[2 * nj + 1][0] = r2v; b[2 * nj + 1][1] = r3;
            }
#pragma unroll
            for (int mi = 0; mi < 2; mi++)
#pragma unroll
                for (int ni = 0; ni < 4; ni++) mma16816(c[mi][ni], a[mi], b[ni]);
        }

        __syncthreads();
#pragma unroll
        for (int mi = 0; mi < 2; mi++) {
#pragma unroll
            for (int rr = 0; rr < 2; rr++) {
                int lr = wm * 32 + mi * 16 + (lane >> 2) + rr * 8;
                float wv = wrow[lr];
#pragma unroll
                for (int ni = 0; ni < 4; ni++) {
                    int col = wn * 32 + ni * 8 + (lane & 3) * 2;
                    float v0 = wv * (c[mi][ni][rr * 2 + 0] + b2s[ci * 128 + col]);
                    float v1 = wv * (c[mi][ni][rr * 2 + 1] + b2s[ci * 128 + col + 1]);
                    __nv_bfloat162 pk;
                    pk.x = __float2bfloat16(v0);
                    pk.y = __float2bfloat16(v1);
                    *(__nv_bfloat162*)(&W2s[sb][lr][col]) = pk;
                }
            }
        }
        __syncthreads();

        for (int i = tid; i < 2048; i += 512) {
            int rr2 = i >> 4, cc = (i & 15) << 3;
            if (rr2 < lim) {
                int v = vrow[rr2];
                uint4 val = *(const uint4*)(&W2s[sb][rr2][cc]);
                *(uint4*)(g_scr + (size_t)v * HD + ci * 128 + cc) = val;
            }
        }
    }
}

// ---------------- kernel: combine (+ aux loss in block 0) ----------------
__global__ __launch_bounds__(256) void k_combine(const float* __restrict__ x, float* __restrict__ out,
                                                 int out_size) {
    __shared__ float red[256];
    __shared__ float auxs;
    int n = blockIdx.x;
    int tid = threadIdx.x;
    const float4* xr = (const float4*)(x + (size_t)n * HD);
    float4* o = (float4*)(out + (size_t)n * HD);
    const __nv_bfloat162* s0 = (const __nv_bfloat162*)(g_scr + (size_t)(2 * n) * HD);
    const __nv_bfloat162* s1 = (const __nv_bfloat162*)(g_scr + (size_t)(2 * n + 1) * HD);
#pragma unroll
    for (int j = tid; j < HD / 4; j += 256) {
        float4 a = xr[j];
        __nv_bfloat162 p0 = s0[2 * j], p1 = s0[2 * j + 1];
        __nv_bfloat162 q0 = s1[2 * j], q1 = s1[2 * j + 1];
        float4 r;
        r.x = a.x + __bfloat162float(p0.x) + __bfloat162float(q0.x);
        r.y = a.y + __bfloat162float(p0.y) + __bfloat162float(q0.y);
        r.z = a.z + __bfloat162float(p1.x) + __bfloat162float(q1.x);
        r.w = a.w + __bfloat162float(p1.y) + __bfloat162float(q1.y);
        o[j] = r;
    }

    // block 0: aux loss reduction (disjoint output element)
    if (n == 0 && out_size > NTOK * HD) {
        if (tid == 0) auxs = 0.f;
        float acc[NE];
#pragma unroll
        for (int e = 0; e < NE; e++) acc[e] = 0.f;
        for (int i = tid; i < NTOK / RT; i += 256) {
#pragma unroll
            for (int e = 0; e < NE; e++) acc[e] += g_pp[i * NE + e];
        }
        __syncthreads();
        for (int e = 0; e < NE; e++) {
            red[tid] = acc[e];
            __syncthreads();
            for (int s = 128; s > 0; s >>= 1) {
                if (tid < s) red[tid] += red[tid + s];
                __syncthreads();
            }
            if (tid == 0) {
                float mp = red[0] / (float)NTOK;
                float mf = (float)g_cnt[e] / (float)NTOK;
                auxs += mp * mf;
            }
            __syncthreads();
        }
        if (tid == 0) out[(size_t)NTOK * HD] = auxs * (float)NE;
    }
}

// ---------------- launch ----------------
extern "C" void kernel_launch(void* const* d_in, const int* in_sizes, int n_in,
                              void* d_out, int out_size) {
    const float* x     = (const float*)d_in[0];
    const float* skin  = (const float*)d_in[1];
    const float* Wimg  = (const float*)d_in[2];
    const float* Wskin = (const float*)d_in[3];
    const float* W1    = (const float*)d_in[4];
    const float* b1    = (const float*)d_in[5];
    const float* W2    = (const float*)d_in[6];
    const float* b2    = (const float*)d_in[7];
    float* out = (float*)d_out;

    cudaFuncSetAttribute(k_moe, cudaFuncAttributeMaxDynamicSharedMemorySize, FM_SMEM);

    k_convert<<<2048, 256>>>(W1, W2);
    k_router<<<NTOK / RT, 512>>>(x, skin, Wimg, Wskin);
    k_moe<<<dim3(NTOK / 128, NE), 512, FM_SMEM>>>(b1, b2);
    k_combine<<<NTOK, 256>>>(x, out, out_size);
}